// round 17
// baseline (speedup 1.0000x reference)
#include <cuda_runtime.h>
#include <cuda_fp16.h>
#include <cstdint>

#define NCTA 128
#define NTHR 512
#define OFF_STA 131072                       // after 128KB resident w
#define OFF_MB  (131072 + 4 * 16384)         // mbarriers after 4 A slots
#define SMEM_MAIN (OFF_MB + 128)             // 196736

// ---------------- device scratch ----------------
__device__ __align__(128) unsigned char g_hpack[1048576]; // [b1024][k512] fp16 h
__device__ __align__(128) unsigned char g_wpack[2097152]; // [n2048 perm][k512] fp16 w
__device__ float g_xT[512 * 1024];
__device__ float g_xdec[48 * 1024];
__device__ __align__(128) unsigned g_cnt8[256];   // 8 group counters (decoder only)
__device__ __align__(128) unsigned g_flag[4096];  // 128 per-CTA step flags, 128B apart

__device__ __forceinline__ float tanha(float x) {
    float r;
    asm("tanh.approx.f32 %0, %1;" : "=f"(r) : "f"(x));
    return r;
}
__device__ __forceinline__ float sigm(float x) {
    return fmaf(tanha(0.5f * x), 0.5f, 0.5f);
}
__device__ __forceinline__ void cpa16(unsigned dst, const void* src) {
    asm volatile("cp.async.cg.shared.global [%0], [%1], 16;" :: "r"(dst), "l"(src));
}
__device__ __forceinline__ void ldmx4(uint32_t& r0, uint32_t& r1, uint32_t& r2,
                                      uint32_t& r3, unsigned a) {
    asm volatile("ldmatrix.sync.aligned.m8n8.x4.shared.b16 {%0,%1,%2,%3}, [%4];"
        : "=r"(r0), "=r"(r1), "=r"(r2), "=r"(r3) : "r"(a));
}
__device__ __forceinline__ void mma16816(float* d, const uint32_t* a,
                                         uint32_t b0, uint32_t b1) {
    asm volatile("mma.sync.aligned.m16n8k16.row.col.f32.f16.f16.f32 "
        "{%0,%1,%2,%3}, {%4,%5,%6,%7}, {%8,%9}, {%0,%1,%2,%3};"
        : "+f"(d[0]), "+f"(d[1]), "+f"(d[2]), "+f"(d[3])
        : "r"(a[0]), "r"(a[1]), "r"(a[2]), "r"(a[3]), "r"(b0), "r"(b1));
}

#define MBINIT(a, n) \
    asm volatile("mbarrier.init.shared.b64 [%0], %1;" :: "r"(a), "r"(n) : "memory")
// .noinc is load-bearing (R15 deadlock with the default incrementing form).
#define CPA_MBARR(a) \
    asm volatile("cp.async.mbarrier.arrive.noinc.shared::cta.b64 [%0];" \
                 :: "r"(a) : "memory")
#define MB_ARRIVE(a) \
    asm volatile("{\n\t.reg .b64 s;\n\tmbarrier.arrive.shared::cta.b64 s, [%0];\n\t}" \
                 :: "r"(a) : "memory")
#define MBWAIT(mb, ph) do { unsigned _ok;                                     \
    asm volatile("{\n\t.reg .pred p;\n\t"                                     \
        "mbarrier.try_wait.parity.shared::cta.b64 p, [%1], %2;\n\t"           \
        "selp.b32 %0,1,0,p;\n\t}" : "=r"(_ok) : "r"(mb), "r"(ph) : "memory"); \
    while (!_ok) {                                                            \
        asm volatile("{\n\t.reg .pred p;\n\t"                                 \
            "mbarrier.try_wait.parity.shared::cta.b64 p, [%1], %2, 0x989680;\n\t" \
            "selp.b32 %0,1,0,p;\n\t}" : "=r"(_ok) : "r"(mb), "r"(ph) : "memory"); } \
} while (0)

// spin until *p >= tgt (producer progress flag)
#define WAITFLAG(p, tgt) do { unsigned _v;                                    \
    asm volatile("ld.acquire.gpu.global.u32 %0, [%1];"                        \
                 : "=r"(_v) : "l"(p) : "memory");                             \
    while (_v < (tgt)) {                                                      \
        __nanosleep(64);                                                      \
        asm volatile("ld.acquire.gpu.global.u32 %0, [%1];"                    \
                     : "=r"(_v) : "l"(p) : "memory");                         \
    }                                                                         \
} while (0)

// ---------------- merged prologue kernel ----------------
extern "C" __global__ void prep_all(const float* __restrict__ x,
                                    const float* __restrict__ w_hh) {
    int bid = blockIdx.x, tid = threadIdx.x;
    int n = bid * 256 + tid;                        // 0..524287
    int b = n >> 9, t = n & 511;
    g_xT[t * 1024 + b] = x[n];                      // x[b][t][0]
    if (n < 262144) ((uint32_t*)g_hpack)[n] = 0u;   // zero h plane (1MB)
    if (n < 48 * 1024) g_xdec[n] = 0.f;
    if (n < 256) g_cnt8[n] = 0u;
    if (n < 4096) g_flag[n] = 0u;
    int ng = bid;
    int j = ng >> 7, nl = ng & 127;
    int wn = nl >> 5, gate = (nl >> 3) & 3, ul = nl & 7;
    int row = gate * 512 + j * 32 + wn * 8 + ul;
    ((__half*)g_wpack)[(size_t)ng * 512 + tid] =
        __float2half_rn(w_hh[row * 512 + tid]);
    ((__half*)g_wpack)[(size_t)ng * 512 + tid + 256] =
        __float2half_rn(w_hh[row * 512 + tid + 256]);
}

// ---------------- main persistent kernel ----------------
extern "C" __global__ void __launch_bounds__(NTHR, 1)
lstm_mma(const float* __restrict__ w_ih, const float* __restrict__ b_ih,
         const float* __restrict__ b_hh, const float* __restrict__ w_fc,
         const float* __restrict__ b_fc, float* __restrict__ dout)
{
    extern __shared__ __align__(1024) char smem[];
    const unsigned sa = (unsigned)__cvta_generic_to_shared(smem);
    const unsigned mb_full  = sa + OFF_MB;        // 8 x 8B
    const unsigned mb_empty = sa + OFF_MB + 64;   // 4 x 8B

    const int tid = threadIdx.x;
    const int lane = tid & 31, w = tid >> 5;   // 16 warps
    const int wm = w >> 2, wn = w & 3;         // 4x4 warp grid, m32 x n32
    const int ql = lane & 3, qr = lane >> 2;
    const int i = blockIdx.x & 7, j = blockIdx.x >> 3;
    unsigned* const cptr   = g_cnt8 + (i << 5);         // decoder group counter
    unsigned* const flbase = g_flag + (i << 9);         // 16 producer flags
    unsigned* const flself = flbase + (j << 5);

    // per-thread constants
    float bs[4][2], ws[4][2], wfc_r[2];
    #pragma unroll
    for (int d = 0; d < 2; ++d) {
        int u = j * 32 + wn * 8 + 2 * ql + d;
        wfc_r[d] = w_fc[u];
        #pragma unroll
        for (int g = 0; g < 4; ++g) {
            int row = g * 512 + u;
            bs[g][d] = b_ih[row] + b_hh[row];
            ws[g][d] = w_ih[row];
        }
    }
    const float bfc = b_fc[0];
    int bth[2][2];
    #pragma unroll
    for (int mt = 0; mt < 2; ++mt)
        #pragma unroll
        for (int hh = 0; hh < 2; ++hh)
            bth[mt][hh] = i * 128 + wm * 32 + mt * 16 + qr + 8 * hh;
    const int kpos = j * 32 + wn * 8 + 2 * ql;

    // ---- resident w: 8 panels of [128 rows][64 k] fp16, SW128 swizzled ----
    for (int idx = tid; idx < 8192; idx += NTHR) {
        int c = idx >> 10, r = (idx >> 3) & 127, q = idx & 7;
        unsigned dst = sa + (unsigned)(c * 16384 + r * 128 + ((q ^ (r & 7)) * 16));
        const char* src = (const char*)g_wpack +
            ((size_t)(j * 128 + r)) * 1024 + c * 128 + q * 16;
        cpa16(dst, src);
    }
    asm volatile("cp.async.commit_group;\n\tcp.async.wait_group 0;" ::: "memory");
    if (tid == 0) {
        #pragma unroll
        for (int c = 0; c < 8; ++c) MBINIT(mb_full + c * 8, NTHR);
        #pragma unroll
        for (int s = 0; s < 4; ++s) MBINIT(mb_empty + s * 8, 16);
    }
    __syncthreads();

    // A staging: chunk = 128 rows x 128B (k64); 2x16B per thread
    const int sr = tid >> 2, sq = tid & 3;
    const char* pA0 = (const char*)g_hpack + (size_t)(i * 128 + sr) * 1024 + sq * 32;
    const unsigned sdst = sa + OFF_STA + (unsigned)(sr * 128);
    const unsigned swo0 = (unsigned)((((sq * 2)     ^ (sr & 7))) << 4);
    const unsigned swo1 = (unsigned)((((sq * 2 + 1) ^ (sr & 7))) << 4);

    // ldmatrix thread bases
    const int rl = lane & 15, qsel = lane >> 4, sw7 = rl & 7;
    const unsigned thA = (unsigned)((wm * 32 + rl) * 128);
    const unsigned thB = (unsigned)((wn * 32 + rl) * 128);

    float cst[2][4];
    #pragma unroll
    for (int mt = 0; mt < 2; ++mt)
        #pragma unroll
        for (int e = 0; e < 4; ++e) cst[mt][e] = 0.f;

    for (int t = 0; t < 560; ++t) {
        const unsigned ph = (unsigned)(t & 1);
        const unsigned tt = (unsigned)t;

        // encoder x loads: static data, no cross-CTA dependency
        float xtv[2][2];
        if (t < 512) {
            #pragma unroll
            for (int mt = 0; mt < 2; ++mt)
                #pragma unroll
                for (int hh = 0; hh < 2; ++hh)
                    xtv[mt][hh] = g_xT[t * 1024 + bth[mt][hh]];
        }

        // stage chunks 0..3: wait ONLY the two producers of each chunk
        #pragma unroll
        for (int c0 = 0; c0 < 4; ++c0) {
            if (t > 0) {
                WAITFLAG(flbase + (c0 * 2) * 32, tt);
                WAITFLAG(flbase + (c0 * 2 + 1) * 32, tt);
            }
            unsigned db = sdst + (unsigned)(c0 * 16384);
            const char* a0 = pA0 + c0 * 128;
            cpa16(db + swo0, a0);
            cpa16(db + swo1, a0 + 16);
            CPA_MBARR(mb_full + (unsigned)(c0 * 8));
        }

        if (t >= 512) {
            // xdec needs all 16 j-contributions: group counter (decoder only)
            if (tid == 0) {
                unsigned tgt = (unsigned)((t - 511) << 4);
                unsigned v;
                do {
                    asm volatile("ld.acquire.gpu.global.u32 %0, [%1];"
                                 : "=r"(v) : "l"(cptr) : "memory");
                    if (v < tgt) __nanosleep(64);
                } while (v < tgt);
            }
            __syncthreads();
            int p = t - 512;
            #pragma unroll
            for (int mt = 0; mt < 2; ++mt)
                #pragma unroll
                for (int hh = 0; hh < 2; ++hh) {
                    xtv[mt][hh] = __ldcg(&g_xdec[p * 1024 + bth[mt][hh]]) + bfc;
                    if (j == 0 && wn == 0 && ql == 0)
                        dout[bth[mt][hh] * 48 + p] = xtv[mt][hh];
                }
            if (t == 559) break;
        }

        float D[2][4][4];
        #pragma unroll
        for (int mt = 0; mt < 2; ++mt)
            #pragma unroll
            for (int nt = 0; nt < 4; ++nt)
                #pragma unroll
                for (int e = 0; e < 4; ++e) D[mt][nt][e] = 0.f;

        // ---- GEMM: 8 k64 chunks, mbarrier ring ----
        #pragma unroll 1
        for (int c = 0; c < 8; ++c) {
            MBWAIT(mb_full + (unsigned)(c * 8), ph);
            const unsigned stA = sa + OFF_STA + (unsigned)((c & 3) * 16384);
            const unsigned stB = sa + (unsigned)(c * 16384);

            uint32_t Af[4][2][4], Bf[4][4][2];
            #pragma unroll
            for (int k16 = 0; k16 < 4; ++k16) {
                unsigned swz = (unsigned)((((k16 * 2 + qsel) ^ sw7)) << 4);
                #pragma unroll
                for (int nb = 0; nb < 2; ++nb) {
                    uint32_t r0, r1, r2, r3;
                    ldmx4(r0, r1, r2, r3, stB + thB + nb * 2048 + swz);
                    Bf[k16][2 * nb][0] = r0; Bf[k16][2 * nb][1] = r2;
                    Bf[k16][2 * nb + 1][0] = r1; Bf[k16][2 * nb + 1][1] = r3;
                }
                #pragma unroll
                for (int mt = 0; mt < 2; ++mt)
                    ldmx4(Af[k16][mt][0], Af[k16][mt][1],
                          Af[k16][mt][2], Af[k16][mt][3],
                          stA + thA + mt * 2048 + swz);
            }
            if (c < 4 && lane == 0)
                MB_ARRIVE(mb_empty + (unsigned)(c * 8));

            #pragma unroll
            for (int k16 = 0; k16 < 4; ++k16)
                #pragma unroll
                for (int mt = 0; mt < 2; ++mt)
                    #pragma unroll
                    for (int nt = 0; nt < 4; ++nt)
                        mma16816(D[mt][nt], Af[k16][mt],
                                 Bf[k16][nt][0], Bf[k16][nt][1]);

            // refill slot c with chunk c+4 (producers 2c+8, 2c+9)
            if (c < 4) {
                MBWAIT(mb_empty + (unsigned)(c * 8), ph);
                if (t > 0) {
                    WAITFLAG(flbase + (2 * c + 8) * 32, tt);
                    WAITFLAG(flbase + (2 * c + 9) * 32, tt);
                }
                unsigned db = sdst + (unsigned)(c * 16384);
                const char* a0 = pA0 + (c + 4) * 128;
                cpa16(db + swo0, a0);
                cpa16(db + swo1, a0 + 16);
                CPA_MBARR(mb_full + (unsigned)((c + 4) * 8));
            }
        }

        // ---- epilogue: gates, c/h update, h store, fc ----
        #pragma unroll
        for (int mt = 0; mt < 2; ++mt) {
            #pragma unroll
            for (int hh = 0; hh < 2; ++hh) {
                float xt = xtv[mt][hh];
                float hv2[2];
                #pragma unroll
                for (int d = 0; d < 2; ++d) {
                    int e = hh * 2 + d;
                    float gi = D[mt][0][e] + bs[0][d] + xt * ws[0][d];
                    float gf = D[mt][1][e] + bs[1][d] + xt * ws[1][d];
                    float gg = D[mt][2][e] + bs[2][d] + xt * ws[2][d];
                    float go = D[mt][3][e] + bs[3][d] + xt * ws[3][d];
                    float c2 = sigm(gf) * cst[mt][e] + sigm(gi) * tanha(gg);
                    cst[mt][e] = c2;
                    hv2[d] = sigm(go) * tanha(c2);
                }
                __half h0 = __float2half_rn(hv2[0]);
                __half h1 = __float2half_rn(hv2[1]);
                uint32_t hiu = (uint32_t)__half_as_ushort(h0) |
                               ((uint32_t)__half_as_ushort(h1) << 16);
                size_t off = (size_t)bth[mt][hh] * 1024 + (size_t)kpos * 2;
                *(uint32_t*)((char*)g_hpack + off) = hiu;

                if (t >= 511) {
                    float pa = hv2[0] * wfc_r[0] + hv2[1] * wfc_r[1];
                    pa += __shfl_xor_sync(0xFFFFFFFFu, pa, 1);
                    pa += __shfl_xor_sync(0xFFFFFFFFu, pa, 2);
                    if (ql == 0)
                        atomicAdd(&g_xdec[(t - 511) * 1024 + bth[mt][hh]], pa);
                }
            }
        }

        // ---- publish progress: h slice (and decoder counter) ----
        __syncthreads();
        if (tid == 0) {
            asm volatile("red.release.gpu.global.add.u32 [%0], 1;"
                         :: "l"(flself) : "memory");
            if (t >= 511)
                asm volatile("red.release.gpu.global.add.u32 [%0], 1;"
                             :: "l"(cptr) : "memory");
        }
    }
}

extern "C" void kernel_launch(void* const* d_in, const int* in_sizes, int n_in,
                              void* d_out, int out_size) {
    (void)in_sizes; (void)n_in; (void)out_size;
    cudaFuncSetAttribute(lstm_mma, cudaFuncAttributeMaxDynamicSharedMemorySize,
                         SMEM_MAIN);
    prep_all<<<2048, 256>>>((const float*)d_in[0], (const float*)d_in[2]);
    lstm_mma<<<NCTA, NTHR, SMEM_MAIN>>>(
        (const float*)d_in[1],   // w_ih
        (const float*)d_in[3],   // b_ih
        (const float*)d_in[4],   // b_hh
        (const float*)d_in[5],   // w_fc
        (const float*)d_in[6],   // b_fc
        (float*)d_out);
}